// round 16
// baseline (speedup 1.0000x reference)
#include <cuda_runtime.h>
#include <cuda_fp16.h>

#define NMAX 50000
#define EMAX 800000
#define FEAT 64
#define BN_EPS 1e-5f

// Scratch (allocation-free). Referenced ONLY inside device code.
__device__ __half   g_bufAh[NMAX * FEAT]; // GEMM output h, fp16 (gather operand)
__device__ float    g_bufB[NMAX * FEAT];  // layer-1 agg / BN buffer (fp32)
__device__ float    g_dinv[NMAX];         // rsqrt(deg)
__device__ float    g_stats[256];         // sums/sumsq for BN1, BN2
__device__ int      g_cnt[NMAX];          // in-degree histogram (zero at sequence exit)
__device__ int      g_rowptr[NMAX];       // block-RELATIVE CSR prefix (ends after fill)
__device__ int      g_bsum[256];          // scan block sums
__device__ int      g_bsoff[256];         // exclusive-scanned block offsets
__device__ int      g_tick;               // scan completion ticket (zero at exit)
__device__ unsigned g_edge[EMAX];         // dst-sorted, packed: (src16<<16)|fp16(w)

// Per-block edge-dtype detection (int64 => odd int32 words all zero).
__device__ __forceinline__ int detect_is64(const void* ei, int* s64) {
    if (threadIdx.x < 32) {
        int nz = ((const int*)ei)[2 * threadIdx.x + 1] != 0;
        unsigned m = __ballot_sync(0xFFFFFFFFu, nz);
        if (threadIdx.x == 0) *s64 = (m == 0u) ? 1 : 0;
    }
    __syncthreads();
    return *s64;
}

// Narrow fetch: ids < 2^31, so int64 entries need only the low 4B word.
__device__ __forceinline__ int edge_at(const void* ei, int pos, int is64) {
    return is64 ? ((const int*)ei)[2 * pos] : ((const int*)ei)[pos];
}

// ---------------------------------------------------------------------------
// 8 edges per thread (MLP=8), 4B loads.
__global__ void k_hist(const void* ei, int E) {
    __shared__ int s64;
    int is64 = detect_is64(ei, &s64);
    int t = blockIdx.x * blockDim.x + threadIdx.x;
    int d[8];
#pragma unroll
    for (int u = 0; u < 8; u++) {
        int e = 8 * t + u;
        d[u] = (e < E) ? edge_at(ei, E + e, is64) : -1;
    }
#pragma unroll
    for (int u = 0; u < 8; u++)
        if (d[u] >= 0) atomicAdd(&g_cnt[d[u]], 1);
}

// Scan: 256 elems/block, block-relative prefix into g_rowptr; block total into
// g_bsum. The LAST block (atomic ticket) exclusive-scans g_bsum -> g_bsoff.
// Block 0 zeros BN stats. dinv computed inline.
__global__ void k_scan(int n, int nb) {
    __shared__ int ts[256];
    __shared__ int lastf;
    int tid = threadIdx.x;
    int i = blockIdx.x * 256 + tid;
    int c = (i < n) ? g_cnt[i] : 0;
    ts[tid] = c;
    __syncthreads();
#pragma unroll
    for (int off = 1; off < 256; off <<= 1) {   // Kogge-Stone inclusive
        int v = (tid >= off) ? ts[tid - off] : 0;
        __syncthreads();
        ts[tid] += v;
        __syncthreads();
    }
    if (tid == 255) g_bsum[blockIdx.x] = ts[255];
    if (i < n) {
        g_rowptr[i] = ts[tid] - c;              // block-relative exclusive
        g_dinv[i] = rsqrtf((float)(c + 1));
    }
    if (blockIdx.x == 0) g_stats[tid] = 0.0f;

    __threadfence();                            // publish bsum before ticket
    __syncthreads();
    if (tid == 0) lastf = (atomicAdd(&g_tick, 1) == nb - 1) ? 1 : 0;
    __syncthreads();
    if (lastf) {                                // last block: scan block sums
        __threadfence();                        // acquire other blocks' bsum
        int v = (tid < nb) ? g_bsum[tid] : 0;
        ts[tid] = v;
        __syncthreads();
#pragma unroll
        for (int off = 1; off < 256; off <<= 1) {
            int u = (tid >= off) ? ts[tid - off] : 0;
            __syncthreads();
            ts[tid] += u;
            __syncthreads();
        }
        g_bsoff[tid] = ts[tid] - v;             // exclusive
        if (tid == 0) g_tick = 0;               // reset for next sequence
    }
}

// Scatter edges into dst-sorted order (8 edges/thread, 4B loads).
// Absolute position = relative rowptr RMW + block offset.
__global__ void k_fill(const void* ei, int E) {
    __shared__ int s64;
    int is64 = detect_is64(ei, &s64);
    int t = blockIdx.x * blockDim.x + threadIdx.x;
    int s[8], d[8];
#pragma unroll
    for (int u = 0; u < 8; u++) {
        int e = 8 * t + u;
        if (e < E) { s[u] = edge_at(ei, e, is64); d[u] = edge_at(ei, E + e, is64); }
        else       { s[u] = -1; d[u] = -1; }
    }
#pragma unroll
    for (int u = 0; u < 8; u++) {
        if (d[u] >= 0) {
            int pos = atomicAdd(&g_rowptr[d[u]], 1) + g_bsoff[d[u] >> 8];
            float w = g_dinv[s[u]] * g_dinv[d[u]];
            unsigned pk = ((unsigned)s[u] << 16) |
                          (unsigned)__half_as_ushort(__float2half_rn(w));
            g_edge[pos] = pk;
        }
    }
}

// ---------------------------------------------------------------------------
// Y[n,64] = X[n,K] @ W[K,64]. 128x64 tile/block, 8x4 register tile/thread.
// Output written as fp16 into g_bufAh. FUSE: BN1+ReLU applied to X on load.
template <int K, bool FUSE>
__global__ void k_gemm(const float* xp, const float* __restrict__ W,
                       const float* __restrict__ gamma, const float* __restrict__ beta,
                       int n, float inv_n) {
    const float* __restrict__ X = xp ? xp : g_bufB;
    __shared__ __align__(16) float sW[64 * 64];
    __shared__ __align__(16) float sX[128 * 64];
    __shared__ float sc[64], bi[64];
    const int tid = threadIdx.x;

    if (FUSE && tid < 64) {
        float mean = g_stats[tid] * inv_n;
        float var  = g_stats[64 + tid] * inv_n - mean * mean;
        float s = rsqrtf(var + BN_EPS) * gamma[tid];
        sc[tid] = s;
        bi[tid] = beta[tid] - mean * s;
    }

    const int row0 = blockIdx.x * 128;
    const int r0 = (tid >> 4) << 3;
    const int c0 = (tid & 15) << 2;
    float acc[8][4] = {};

    for (int kb = 0; kb < K; kb += 64) {
        __syncthreads();
        for (int idx = tid; idx < 64 * 16; idx += 256)
            reinterpret_cast<float4*>(sW)[idx] =
                reinterpret_cast<const float4*>(W + kb * 64)[idx];
        for (int idx = tid; idx < 128 * 16; idx += 256) {
            int r = idx >> 4, k4 = (idx & 15) << 2;
            int row = row0 + r;
            float4 v = (row < n)
                ? *reinterpret_cast<const float4*>(&X[row * K + kb + k4])
                : make_float4(0.f, 0.f, 0.f, 0.f);
            if (FUSE) {
                v.x = fmaxf(fmaf(v.x, sc[k4],     bi[k4]),     0.f);
                v.y = fmaxf(fmaf(v.y, sc[k4 + 1], bi[k4 + 1]), 0.f);
                v.z = fmaxf(fmaf(v.z, sc[k4 + 2], bi[k4 + 2]), 0.f);
                v.w = fmaxf(fmaf(v.w, sc[k4 + 3], bi[k4 + 3]), 0.f);
            }
            reinterpret_cast<float4*>(sX)[idx] = v;
        }
        __syncthreads();
#pragma unroll 8
        for (int kk = 0; kk < 64; kk++) {
            float4 b = *reinterpret_cast<const float4*>(&sW[kk * 64 + c0]);
#pragma unroll
            for (int i = 0; i < 8; i++) {
                float a = sX[(r0 + i) * 64 + kk];
                acc[i][0] += a * b.x;
                acc[i][1] += a * b.y;
                acc[i][2] += a * b.z;
                acc[i][3] += a * b.w;
            }
        }
    }
    uint2* __restrict__ Ho = reinterpret_cast<uint2*>(g_bufAh);
#pragma unroll
    for (int i = 0; i < 8; i++) {
        int row = row0 + r0 + i;
        if (row < n) {
            __half2 h01 = __floats2half2_rn(acc[i][0], acc[i][1]);
            __half2 h23 = __floats2half2_rn(acc[i][2], acc[i][3]);
            uint2 u;
            u.x = *reinterpret_cast<unsigned*>(&h01);
            u.y = *reinterpret_cast<unsigned*>(&h23);
            Ho[row * 16 + (c0 >> 2)] = u;
        }
    }
}

// ---------------------------------------------------------------------------
// Aggregation: 8 lanes per node (uint4 = 8 fp16 feats/lane), 4 nodes per warp.
// Batch = 8 edges, fully unrolled; next batch prefetched; lanes past row end
// supply 0 (srow=0, w=+0). Fewer instrs/feature and less batch padding than
// the 16-lane version. fp32 accumulate.
__global__ void k_agg(float* aggp, int soff, int n) {
    float4* __restrict__ agg = reinterpret_cast<float4*>(aggp ? aggp : g_bufB);
    const uint4* __restrict__ Hh = reinterpret_cast<const uint4*>(g_bufAh);
    __shared__ float ssum[64], ssq[64];
    const int tid  = threadIdx.x;
    const int lane = tid & 7;                        // feature octet within node
    const unsigned gmask = 0xFFu << (tid & 0x18);    // this 8-lane group
    const int node = blockIdx.x * 32 + (tid >> 3);

    if (tid < 64) { ssum[tid] = 0.0f; ssq[tid] = 0.0f; }
    __syncthreads();

    float acc[8] = {};
    if (node < n) {
        int end   = g_rowptr[node] + g_bsoff[node >> 8];
        int start = node ? (g_rowptr[node - 1] + g_bsoff[(node - 1) >> 8]) : 0;
        float dd  = g_dinv[node];
        dd *= dd;
        uint4 hv = Hh[node * 8 + lane];
        const __half2* hp = reinterpret_cast<const __half2*>(&hv);
#pragma unroll
        for (int p = 0; p < 4; p++) {
            float2 f = __half22float2(hp[p]);
            acc[2 * p]     = f.x * dd;
            acc[2 * p + 1] = f.y * dd;
        }

        unsigned pk = (start + lane < end) ? g_edge[start + lane] : 0u;
        for (int base = start; base < end; base += 8) {
            unsigned cur = pk;
            int j2 = base + 8 + lane;                // prefetch next batch
            pk = (j2 < end) ? g_edge[j2] : 0u;
#pragma unroll
            for (int k = 0; k < 8; k++) {
                unsigned pv = __shfl_sync(gmask, cur, k, 8);
                int   srow = (int)(pv >> 16);
                float w    = __half2float(__ushort_as_half((unsigned short)(pv & 0xFFFFu)));
                uint4 v = Hh[srow * 8 + lane];
                const __half2* vp = reinterpret_cast<const __half2*>(&v);
#pragma unroll
                for (int p = 0; p < 4; p++) {
                    float2 f = __half22float2(vp[p]);
                    acc[2 * p]     += f.x * w;
                    acc[2 * p + 1] += f.y * w;
                }
            }
        }
        agg[node * 16 + lane * 2]     = make_float4(acc[0], acc[1], acc[2], acc[3]);
        agg[node * 16 + lane * 2 + 1] = make_float4(acc[4], acc[5], acc[6], acc[7]);
    }
    // Stats: reduce the 4 node-groups (strides 16, 8), then 8 lanes atomically
    // add their 8 features. Inactive nodes contribute zeros.
    float s[8], q[8];
#pragma unroll
    for (int u = 0; u < 8; u++) { s[u] = acc[u]; q[u] = acc[u] * acc[u]; }
#pragma unroll
    for (int u = 0; u < 8; u++) {
        s[u] += __shfl_down_sync(0xFFFFFFFFu, s[u], 16);
        q[u] += __shfl_down_sync(0xFFFFFFFFu, q[u], 16);
        s[u] += __shfl_down_sync(0xFFFFFFFFu, s[u], 8);
        q[u] += __shfl_down_sync(0xFFFFFFFFu, q[u], 8);
    }
    if ((tid & 31) < 8) {
        int f = lane << 3;
#pragma unroll
        for (int u = 0; u < 8; u++) {
            atomicAdd(&ssum[f + u], s[u]);
            atomicAdd(&ssq[f + u],  q[u]);
        }
    }
    __syncthreads();
    if (tid < 64) {
        atomicAdd(&g_stats[soff + tid],      ssum[tid]);
        atomicAdd(&g_stats[soff + 64 + tid], ssq[tid]);
    }
}

// Final BN (layer 2, no ReLU), in-place on out, float4-vectorized.
// Tail: zero g_cnt (invariant: cnt zero at sequence exit).
__global__ void k_bn(float* a, const float* __restrict__ gamma,
                     const float* __restrict__ beta, int n, float inv_n) {
    int idx = blockIdx.x * blockDim.x + threadIdx.x;   // over n*16 float4s
    if (idx < n * 16) {
        int f = (idx & 15) << 2;
        float4 v = reinterpret_cast<float4*>(a)[idx];
#pragma unroll
        for (int u = 0; u < 4; u++) {
            float mean = g_stats[128 + f + u] * inv_n;
            float var  = g_stats[192 + f + u] * inv_n - mean * mean;
            float sc = rsqrtf(var + BN_EPS) * gamma[f + u];
            float bi = beta[f + u] - mean * sc;
            (&v.x)[u] = fmaf((&v.x)[u], sc, bi);
        }
        reinterpret_cast<float4*>(a)[idx] = v;
    }
    if (idx < n) g_cnt[idx] = 0;
}

// ---------------------------------------------------------------------------
extern "C" void kernel_launch(void* const* d_in, const int* in_sizes, int n_in,
                              void* d_out, int out_size) {
    const float* x      = (const float*)d_in[0];
    const void*  ei     = d_in[1];
    const float* W1     = (const float*)d_in[2];
    const float* gamma1 = (const float*)d_in[4];
    const float* beta1  = (const float*)d_in[5];
    const float* W2     = (const float*)d_in[6];
    const float* gamma2 = (const float*)d_in[8];
    const float* beta2  = (const float*)d_in[9];
    float*       out    = (float*)d_out;

    const int n = in_sizes[0] / 128;
    const int E = in_sizes[1] / 2;
    const float inv_n = 1.0f / (float)n;

    const int nBlocks  = (n + 255) / 256;        // 196 (<=256)
    const int e8Blocks = (E + 2047) / 2048;      // 8 edges/thread
    const int gemmGrid = (n + 127) / 128;
    const int aggGrid  = (n + 31) / 32;          // 32 nodes/block
    const int nv4      = (n * 16 + 255) / 256;   // float4 BN grid

    // Fork: GEMM1 runs concurrently with the CSR build chain.
    cudaStream_t s2;
    cudaStreamCreateWithFlags(&s2, cudaStreamNonBlocking);
    cudaEvent_t eF, eJ;
    cudaEventCreateWithFlags(&eF, cudaEventDisableTiming);
    cudaEventCreateWithFlags(&eJ, cudaEventDisableTiming);

    cudaEventRecord(eF, 0);
    cudaStreamWaitEvent(s2, eF, 0);
    k_gemm<128, false><<<gemmGrid, 256, 0, s2>>>(x, W1, nullptr, nullptr, n, inv_n);
    cudaEventRecord(eJ, s2);

    // CSR build + normalization (capture stream): 3 kernels
    k_hist<<<e8Blocks, 256>>>(ei, E);
    k_scan<<<nBlocks, 256>>>(n, nBlocks);
    k_fill<<<e8Blocks, 256>>>(ei, E);

    cudaStreamWaitEvent(0, eJ, 0);   // join GEMM1 before aggregation

    // layer 1: agg [+stats]
    k_agg<<<aggGrid, 256>>>(nullptr, 0, n);
    // layer 2: BN1+ReLU fused into GEMM2's X load -> agg [+stats] -> BN2
    k_gemm<64, true><<<gemmGrid, 256>>>(nullptr, W2, gamma1, beta1, n, inv_n);
    k_agg<<<aggGrid, 256>>>(out, 128, n);
    k_bn<<<nv4, 256>>>(out, gamma2, beta2, n, inv_n);
}

// round 17
// speedup vs baseline: 1.0381x; 1.0381x over previous
#include <cuda_runtime.h>
#include <cuda_fp16.h>

#define NMAX 50000
#define EMAX 800000
#define FEAT 64
#define BN_EPS 1e-5f

// Scratch (allocation-free). Referenced ONLY inside device code.
__device__ __half   g_bufAh[NMAX * FEAT]; // GEMM output h, fp16 (gather operand)
__device__ float    g_bufB[NMAX * FEAT];  // layer-1 agg / BN buffer (fp32)
__device__ float    g_dinv[NMAX];         // rsqrt(deg)
__device__ float    g_stats[256];         // sums/sumsq for BN1, BN2
__device__ int      g_cnt[NMAX];          // in-degree histogram (zero at sequence exit)
__device__ int      g_rowptr[NMAX];       // block-RELATIVE CSR prefix (ends after fill)
__device__ int      g_bsum[256];          // scan block sums
__device__ int      g_bsoff[256];         // exclusive-scanned block offsets
__device__ int      g_tick;               // scan completion ticket (zero at exit)
__device__ unsigned g_edge[EMAX];         // dst-sorted, packed: (src16<<16)|fp16(w)

// Per-block edge-dtype detection (int64 => odd int32 words all zero).
__device__ __forceinline__ int detect_is64(const void* ei, int* s64) {
    if (threadIdx.x < 32) {
        int nz = ((const int*)ei)[2 * threadIdx.x + 1] != 0;
        unsigned m = __ballot_sync(0xFFFFFFFFu, nz);
        if (threadIdx.x == 0) *s64 = (m == 0u) ? 1 : 0;
    }
    __syncthreads();
    return *s64;
}

// Narrow fetch: ids < 2^31, so int64 entries need only the low 4B word.
__device__ __forceinline__ int edge_at(const void* ei, int pos, int is64) {
    return is64 ? ((const int*)ei)[2 * pos] : ((const int*)ei)[pos];
}

// ---------------------------------------------------------------------------
// 2 edges per thread: large grid -> full occupancy (scheduler hides ATOMG).
__global__ void k_hist(const void* ei, int E) {
    __shared__ int s64;
    int is64 = detect_is64(ei, &s64);
    int t = blockIdx.x * blockDim.x + threadIdx.x;
    int d0 = (2 * t     < E) ? edge_at(ei, E + 2 * t,     is64) : -1;
    int d1 = (2 * t + 1 < E) ? edge_at(ei, E + 2 * t + 1, is64) : -1;
    if (d0 >= 0) atomicAdd(&g_cnt[d0], 1);
    if (d1 >= 0) atomicAdd(&g_cnt[d1], 1);
}

// Scan: 256 elems/block, block-relative prefix into g_rowptr; block total into
// g_bsum. The LAST block (atomic ticket) exclusive-scans g_bsum -> g_bsoff.
// Block 0 zeros BN stats. dinv computed inline.
__global__ void k_scan(int n, int nb) {
    __shared__ int ts[256];
    __shared__ int lastf;
    int tid = threadIdx.x;
    int i = blockIdx.x * 256 + tid;
    int c = (i < n) ? g_cnt[i] : 0;
    ts[tid] = c;
    __syncthreads();
#pragma unroll
    for (int off = 1; off < 256; off <<= 1) {   // Kogge-Stone inclusive
        int v = (tid >= off) ? ts[tid - off] : 0;
        __syncthreads();
        ts[tid] += v;
        __syncthreads();
    }
    if (tid == 255) g_bsum[blockIdx.x] = ts[255];
    if (i < n) {
        g_rowptr[i] = ts[tid] - c;              // block-relative exclusive
        g_dinv[i] = rsqrtf((float)(c + 1));
    }
    if (blockIdx.x == 0) g_stats[tid] = 0.0f;

    __threadfence();                            // publish bsum before ticket
    __syncthreads();
    if (tid == 0) lastf = (atomicAdd(&g_tick, 1) == nb - 1) ? 1 : 0;
    __syncthreads();
    if (lastf) {                                // last block: scan block sums
        __threadfence();                        // acquire other blocks' bsum
        int v = (tid < nb) ? g_bsum[tid] : 0;
        ts[tid] = v;
        __syncthreads();
#pragma unroll
        for (int off = 1; off < 256; off <<= 1) {
            int u = (tid >= off) ? ts[tid - off] : 0;
            __syncthreads();
            ts[tid] += u;
            __syncthreads();
        }
        g_bsoff[tid] = ts[tid] - v;             // exclusive
        if (tid == 0) g_tick = 0;               // reset for next sequence
    }
}

// Scatter edges into dst-sorted order (2 edges/thread, large grid).
// Absolute position = relative rowptr RMW + block offset.
__global__ void k_fill(const void* ei, int E) {
    __shared__ int s64;
    int is64 = detect_is64(ei, &s64);
    int t = blockIdx.x * blockDim.x + threadIdx.x;
#pragma unroll
    for (int u = 0; u < 2; u++) {
        int e = 2 * t + u;
        if (e < E) {
            int s = edge_at(ei, e, is64);
            int d = edge_at(ei, E + e, is64);
            int pos = atomicAdd(&g_rowptr[d], 1) + g_bsoff[d >> 8];
            float w = g_dinv[s] * g_dinv[d];
            unsigned pk = ((unsigned)s << 16) |
                          (unsigned)__half_as_ushort(__float2half_rn(w));
            g_edge[pos] = pk;
        }
    }
}

// ---------------------------------------------------------------------------
// Y[n,64] = X[n,K] @ W[K,64]. 128x64 tile/block, 8x4 register tile/thread.
// Output written as fp16 into g_bufAh. FUSE: BN1+ReLU applied to X on load.
template <int K, bool FUSE>
__global__ void k_gemm(const float* xp, const float* __restrict__ W,
                       const float* __restrict__ gamma, const float* __restrict__ beta,
                       int n, float inv_n) {
    const float* __restrict__ X = xp ? xp : g_bufB;
    __shared__ __align__(16) float sW[64 * 64];
    __shared__ __align__(16) float sX[128 * 64];
    __shared__ float sc[64], bi[64];
    const int tid = threadIdx.x;

    if (FUSE && tid < 64) {
        float mean = g_stats[tid] * inv_n;
        float var  = g_stats[64 + tid] * inv_n - mean * mean;
        float s = rsqrtf(var + BN_EPS) * gamma[tid];
        sc[tid] = s;
        bi[tid] = beta[tid] - mean * s;
    }

    const int row0 = blockIdx.x * 128;
    const int r0 = (tid >> 4) << 3;
    const int c0 = (tid & 15) << 2;
    float acc[8][4] = {};

    for (int kb = 0; kb < K; kb += 64) {
        __syncthreads();
        for (int idx = tid; idx < 64 * 16; idx += 256)
            reinterpret_cast<float4*>(sW)[idx] =
                reinterpret_cast<const float4*>(W + kb * 64)[idx];
        for (int idx = tid; idx < 128 * 16; idx += 256) {
            int r = idx >> 4, k4 = (idx & 15) << 2;
            int row = row0 + r;
            float4 v = (row < n)
                ? *reinterpret_cast<const float4*>(&X[row * K + kb + k4])
                : make_float4(0.f, 0.f, 0.f, 0.f);
            if (FUSE) {
                v.x = fmaxf(fmaf(v.x, sc[k4],     bi[k4]),     0.f);
                v.y = fmaxf(fmaf(v.y, sc[k4 + 1], bi[k4 + 1]), 0.f);
                v.z = fmaxf(fmaf(v.z, sc[k4 + 2], bi[k4 + 2]), 0.f);
                v.w = fmaxf(fmaf(v.w, sc[k4 + 3], bi[k4 + 3]), 0.f);
            }
            reinterpret_cast<float4*>(sX)[idx] = v;
        }
        __syncthreads();
#pragma unroll 8
        for (int kk = 0; kk < 64; kk++) {
            float4 b = *reinterpret_cast<const float4*>(&sW[kk * 64 + c0]);
#pragma unroll
            for (int i = 0; i < 8; i++) {
                float a = sX[(r0 + i) * 64 + kk];
                acc[i][0] += a * b.x;
                acc[i][1] += a * b.y;
                acc[i][2] += a * b.z;
                acc[i][3] += a * b.w;
            }
        }
    }
    uint2* __restrict__ Ho = reinterpret_cast<uint2*>(g_bufAh);
#pragma unroll
    for (int i = 0; i < 8; i++) {
        int row = row0 + r0 + i;
        if (row < n) {
            __half2 h01 = __floats2half2_rn(acc[i][0], acc[i][1]);
            __half2 h23 = __floats2half2_rn(acc[i][2], acc[i][3]);
            uint2 u;
            u.x = *reinterpret_cast<unsigned*>(&h01);
            u.y = *reinterpret_cast<unsigned*>(&h23);
            Ho[row * 16 + (c0 >> 2)] = u;
        }
    }
}

// ---------------------------------------------------------------------------
// Aggregation: 16 lanes per node, 2 nodes per warp, half-warp shfl masks.
// Packed edges, ONE shfl per step, next batch prefetched.
__global__ void k_agg(float* aggp, int soff, int n) {
    float4* __restrict__ agg = reinterpret_cast<float4*>(aggp ? aggp : g_bufB);
    const uint2* __restrict__ Hh = reinterpret_cast<const uint2*>(g_bufAh);
    __shared__ float ssum[64], ssq[64];
    const int tid  = threadIdx.x;
    const int lane = tid & 15;
    const unsigned hmask = 0xFFFFu << (tid & 0x10);
    const int node = blockIdx.x * 16 + (tid >> 4);

    if (tid < 64) { ssum[tid] = 0.0f; ssq[tid] = 0.0f; }
    __syncthreads();

    float4 acc = make_float4(0.f, 0.f, 0.f, 0.f);
    if (node < n) {
        int end   = g_rowptr[node] + g_bsoff[node >> 8];
        int start = node ? (g_rowptr[node - 1] + g_bsoff[(node - 1) >> 8]) : 0;
        float di  = g_dinv[node];
        float dd  = di * di;
        uint2 hv  = Hh[node * 16 + lane];
        float2 f0 = __half22float2(*reinterpret_cast<__half2*>(&hv.x));
        float2 f1 = __half22float2(*reinterpret_cast<__half2*>(&hv.y));
        acc = make_float4(f0.x * dd, f0.y * dd, f1.x * dd, f1.y * dd);

        unsigned pk = (start + lane < end) ? g_edge[start + lane] : 0u;
        for (int base = start; base < end; base += 16) {
            unsigned cur = pk;
            int j2 = base + 16 + lane;                 // prefetch next batch
            pk = (j2 < end) ? g_edge[j2] : 0u;
#pragma unroll
            for (int k = 0; k < 16; k++) {
                unsigned pv = __shfl_sync(hmask, cur, k, 16);
                int   srow = (int)(pv >> 16);
                float w    = __half2float(__ushort_as_half((unsigned short)(pv & 0xFFFFu)));
                uint2 v = Hh[srow * 16 + lane];
                float2 a = __half22float2(*reinterpret_cast<__half2*>(&v.x));
                float2 b = __half22float2(*reinterpret_cast<__half2*>(&v.y));
                acc.x += a.x * w;
                acc.y += a.y * w;
                acc.z += b.x * w;
                acc.w += b.y * w;
            }
        }
        agg[node * 16 + lane] = acc;
    }
    // Stats: combine half-warps via shfl, then one atomic set per warp.
    float sx = acc.x, sy = acc.y, sz = acc.z, sw = acc.w;
    float qx = acc.x * acc.x, qy = acc.y * acc.y, qz = acc.z * acc.z, qw = acc.w * acc.w;
    sx += __shfl_down_sync(0xFFFFFFFFu, sx, 16);
    sy += __shfl_down_sync(0xFFFFFFFFu, sy, 16);
    sz += __shfl_down_sync(0xFFFFFFFFu, sz, 16);
    sw += __shfl_down_sync(0xFFFFFFFFu, sw, 16);
    qx += __shfl_down_sync(0xFFFFFFFFu, qx, 16);
    qy += __shfl_down_sync(0xFFFFFFFFu, qy, 16);
    qz += __shfl_down_sync(0xFFFFFFFFu, qz, 16);
    qw += __shfl_down_sync(0xFFFFFFFFu, qw, 16);
    if ((tid & 31) < 16) {
        int f = lane << 2;
        atomicAdd(&ssum[f],     sx);
        atomicAdd(&ssum[f + 1], sy);
        atomicAdd(&ssum[f + 2], sz);
        atomicAdd(&ssum[f + 3], sw);
        atomicAdd(&ssq[f],      qx);
        atomicAdd(&ssq[f + 1],  qy);
        atomicAdd(&ssq[f + 2],  qz);
        atomicAdd(&ssq[f + 3],  qw);
    }
    __syncthreads();
    if (tid < 64) {
        atomicAdd(&g_stats[soff + tid],      ssum[tid]);
        atomicAdd(&g_stats[soff + 64 + tid], ssq[tid]);
    }
}

// Final BN (layer 2, no ReLU), in-place on out, float4-vectorized.
// Tail: zero g_cnt (invariant: cnt zero at sequence exit).
__global__ void k_bn(float* a, const float* __restrict__ gamma,
                     const float* __restrict__ beta, int n, float inv_n) {
    int idx = blockIdx.x * blockDim.x + threadIdx.x;   // over n*16 float4s
    if (idx < n * 16) {
        int f = (idx & 15) << 2;
        float4 v = reinterpret_cast<float4*>(a)[idx];
#pragma unroll
        for (int u = 0; u < 4; u++) {
            float mean = g_stats[128 + f + u] * inv_n;
            float var  = g_stats[192 + f + u] * inv_n - mean * mean;
            float sc = rsqrtf(var + BN_EPS) * gamma[f + u];
            float bi = beta[f + u] - mean * sc;
            (&v.x)[u] = fmaf((&v.x)[u], sc, bi);
        }
        reinterpret_cast<float4*>(a)[idx] = v;
    }
    if (idx < n) g_cnt[idx] = 0;
}

// ---------------------------------------------------------------------------
extern "C" void kernel_launch(void* const* d_in, const int* in_sizes, int n_in,
                              void* d_out, int out_size) {
    const float* x      = (const float*)d_in[0];
    const void*  ei     = d_in[1];
    const float* W1     = (const float*)d_in[2];
    const float* gamma1 = (const float*)d_in[4];
    const float* beta1  = (const float*)d_in[5];
    const float* W2     = (const float*)d_in[6];
    const float* gamma2 = (const float*)d_in[8];
    const float* beta2  = (const float*)d_in[9];
    float*       out    = (float*)d_out;

    const int n = in_sizes[0] / 128;
    const int E = in_sizes[1] / 2;
    const float inv_n = 1.0f / (float)n;

    const int nBlocks  = (n + 255) / 256;        // 196 (<=256)
    const int e2Blocks = (E + 511) / 512;        // 2 edges/thread, big grid
    const int gemmGrid = (n + 127) / 128;
    const int aggGrid  = (n + 15) / 16;
    const int nv4      = (n * 16 + 255) / 256;   // float4 BN grid

    // Fork: GEMM1 runs concurrently with the CSR build chain.
    cudaStream_t s2;
    cudaStreamCreateWithFlags(&s2, cudaStreamNonBlocking);
    cudaEvent_t eF, eJ;
    cudaEventCreateWithFlags(&eF, cudaEventDisableTiming);
    cudaEventCreateWithFlags(&eJ, cudaEventDisableTiming);

    cudaEventRecord(eF, 0);
    cudaStreamWaitEvent(s2, eF, 0);
    k_gemm<128, false><<<gemmGrid, 256, 0, s2>>>(x, W1, nullptr, nullptr, n, inv_n);
    cudaEventRecord(eJ, s2);

    // CSR build + normalization (capture stream): 3 kernels
    k_hist<<<e2Blocks, 256>>>(ei, E);
    k_scan<<<nBlocks, 256>>>(n, nBlocks);
    k_fill<<<e2Blocks, 256>>>(ei, E);

    cudaStreamWaitEvent(0, eJ, 0);   // join GEMM1 before aggregation

    // layer 1: agg [+stats]
    k_agg<<<aggGrid, 256>>>(nullptr, 0, n);
    // layer 2: BN1+ReLU fused into GEMM2's X load -> agg [+stats] -> BN2
    k_gemm<64, true><<<gemmGrid, 256>>>(nullptr, W2, gamma1, beta1, n, inv_n);
    k_agg<<<aggGrid, 256>>>(out, 128, n);
    k_bn<<<nv4, 256>>>(out, gamma2, beta2, n, inv_n);
}